// round 1
// baseline (speedup 1.0000x reference)
#include <cuda_runtime.h>

// Scratch for the extracted diagonal (allocation-free: __device__ global).
__device__ float g_diag[4096];

// Kernel A: pull diag(W) out of the dense [4096,4096] matrix.
// W[j][j] is at linear index j*4096 + j = j*4097.
__global__ void extract_diag_kernel(const float* __restrict__ W) {
    int j = blockIdx.x * blockDim.x + threadIdx.x;
    if (j < 4096) {
        g_diag[j] = __ldg(&W[(long)j * 4097]);
    }
}

// Kernel B: y[t][j] = x[t][j] * diag[j], vectorized as float4.
// TOKENS=8192, IN_FEATURES=4096 -> 8192*4096/4 = 8,388,608 float4 elements.
// Row has 1024 float4; diag float4 index = linear & 1023.
__global__ void diag_scale_kernel(const float4* __restrict__ x,
                                  float4* __restrict__ y) {
    unsigned int i = blockIdx.x * blockDim.x + threadIdx.x;  // < 2^23, fits
    const float4* d4 = reinterpret_cast<const float4*>(g_diag);

    float4 v = x[i];
    float4 d = __ldg(&d4[i & 1023u]);
    v.x *= d.x;
    v.y *= d.y;
    v.z *= d.z;
    v.w *= d.w;
    y[i] = v;
}

extern "C" void kernel_launch(void* const* d_in, const int* in_sizes, int n_in,
                              void* d_out, int out_size) {
    const float* x = (const float*)d_in[0];
    const float* W = (const float*)d_in[1];
    float* y = (float*)d_out;

    // Extract diagonal: 4096 elements.
    extract_diag_kernel<<<16, 256>>>(W);

    // Elementwise scale: 8,388,608 float4 -> 32768 blocks x 256 threads.
    diag_scale_kernel<<<32768, 256>>>((const float4*)x, (float4*)y);
}